// round 2
// baseline (speedup 1.0000x reference)
#include <cuda_runtime.h>
#include <math.h>

#define NB 4096
#define NH 200
#define ROWSTR 68   // floats per staged row: 16B-aligned, 2-way-max bank spread

typedef unsigned long long ull;

__device__ __forceinline__ ull pk2(float a) {
    ull r; asm("mov.b64 %0, {%1, %1};" : "=l"(r) : "f"(a)); return r;
}
__device__ __forceinline__ float2 upk(ull v) {
    float2 f; asm("mov.b64 {%0, %1}, %2;" : "=f"(f.x), "=f"(f.y) : "l"(v)); return f;
}
__device__ __forceinline__ void ffma2(ull& d, ull a, ull b) {
    asm("fma.rn.f32x2 %0, %1, %2, %0;" : "+l"(d) : "l"(a), "l"(b));
}

// One input element for two rows (xiA, xiB) against a 16-wide transposed
// weight slice (16B-aligned SMEM): 4 LDS.128 -> 16 FFMA2 (64 FLOP-pairs).
__device__ __forceinline__ void fstep(ull* aA, ull* aB, const float* w16,
                                      float xiA, float xiB) {
    ull xA = pk2(xiA), xB = pk2(xiB);
    const ulonglong2* w = reinterpret_cast<const ulonglong2*>(w16);
#pragma unroll
    for (int j = 0; j < 4; j++) {
        ulonglong2 wv = w[j];
        ffma2(aA[2*j],   wv.x, xA);
        ffma2(aA[2*j+1], wv.y, xA);
        ffma2(aB[2*j],   wv.x, xB);
        ffma2(aB[2*j+1], wv.y, xB);
    }
}

// 64-input layer, inputs from SMEM rows xA/xB (16B-aligned).
__device__ __forceinline__ void layer64(ull* aA, ull* aB, const float* wT,
                                        const float* xA, const float* xB, int ob) {
#pragma unroll 4
    for (int q4 = 0; q4 < 16; q4++) {
        float4 va = reinterpret_cast<const float4*>(xA)[q4];
        float4 vb = reinterpret_cast<const float4*>(xB)[q4];
        fstep(aA, aB, wT + (4*q4 + 0)*64 + ob, va.x, vb.x);
        fstep(aA, aB, wT + (4*q4 + 1)*64 + ob, va.y, vb.y);
        fstep(aA, aB, wT + (4*q4 + 2)*64 + ob, va.z, vb.z);
        fstep(aA, aB, wT + (4*q4 + 3)*64 + ob, va.w, vb.w);
    }
}

__device__ __forceinline__ void initacc(ull* a, const float* bsrc) {
    const ull* p = reinterpret_cast<const ull*>(bsrc);
#pragma unroll
    for (int j = 0; j < 8; j++) a[j] = p[j];
}

__device__ __forceinline__ void relustore(float* dst, const ull* a) {
#pragma unroll
    for (int j = 0; j < 4; j++) {
        float2 f0 = upk(a[2*j]), f1 = upk(a[2*j+1]);
        reinterpret_cast<float4*>(dst)[j] =
            make_float4(fmaxf(f0.x, 0.f), fmaxf(f0.y, 0.f),
                        fmaxf(f1.x, 0.f), fmaxf(f1.y, 0.f));
    }
}

// SMEM floats: w1T 4160 | w2T 4096 | a1T 8192 | a2T 4096 | bias 512 |
//              ohist 13600 | stg 13600 | lg 256 | red 40  = 48552
#define SMEM_FLOATS 48552
#define SMEM_BYTES  (SMEM_FLOATS * 4)

__global__ __launch_bounds__(512, 1)
void uvagg_kernel(const int* __restrict__ nodes, const int* __restrict__ huv,
                  const float* __restrict__ hr,
                  const float* __restrict__ u2e, const float* __restrict__ v2e,
                  const float* __restrict__ w1, const float* __restrict__ b1,
                  const float* __restrict__ w2, const float* __restrict__ b2,
                  const float* __restrict__ a1w, const float* __restrict__ a1b,
                  const float* __restrict__ a2w, const float* __restrict__ a2b,
                  const float* __restrict__ a3w, const float* __restrict__ a3b,
                  float* __restrict__ out)
{
    extern __shared__ float sm[];
    float* w1T   = sm;                  // [65][64]
    float* w2T   = w1T + 4160;          // [64][64]
    float* a1T   = w2T + 4096;          // [128][64]
    float* a2T   = a1T + 8192;          // [64][64]
    float* bias  = a2T + 4096;          // [b1|b2|upart|a2b|a3w|urep|a3b0]
    float* ohist = bias + 512;          // [200][68]
    float* stg   = ohist + 200*ROWSTR;  // [200][68]
    float* lg    = stg + 200*ROWSTR;    // 256
    float* red   = lg + 256;            // 40

    const int tid = threadIdx.x;
    const int b   = blockIdx.x;

    // ---- Stage weights transposed to i-major ----
    for (int k = tid; k < 4160; k += 512) { int o = k / 65, i = k - o*65; w1T[i*64+o] = w1[k]; }
    for (int k = tid; k < 4096; k += 512) { int o = k >> 6, i = k & 63;   w2T[i*64+o] = w2[k]; }
    for (int k = tid; k < 8192; k += 512) { int o = k >> 7, i = k & 127;  a1T[i*64+o] = a1w[k]; }
    for (int k = tid; k < 4096; k += 512) { int o = k >> 6, i = k & 63;   a2T[i*64+o] = a2w[k]; }
    if (tid < 64) {
        bias[tid]       = b1[tid];
        bias[64 + tid]  = b2[tid];
        bias[192 + tid] = a2b[tid];
        bias[256 + tid] = a3w[tid];
        bias[320 + tid] = u2e[(size_t)nodes[b] * 64 + tid];
    }
    if (tid == 0) bias[384] = a3b[0];
    if (tid >= 200 && tid < 256) lg[tid] = -INFINITY;
    __syncthreads();

    // ---- upart[o] = a1b[o] + sum_i urep[i] * A1[o][64+i]  (shared by all rows) ----
    if (tid < 64) {
        float s = a1b[tid];
#pragma unroll 8
        for (int i = 0; i < 64; i++) s = fmaf(bias[320 + i], a1T[(64 + i)*64 + tid], s);
        bias[128 + tid] = s;
    }
    __syncthreads();

    // ---- Per-row chain: 4 threads per row-pair, 16 outputs each, 2 rows ----
    if (tid < 400) {
        const int g  = tid >> 2;        // 0..99 -> rows 2g, 2g+1
        const int q  = tid & 3;
        const int ob = 16 * q;
        const int hA = 2*g, hB = 2*g + 1;
        const unsigned gm = 0xFu << ((tid & 31) & ~3);  // 4-lane group mask

        const long baseA = (long)b * NH + hA;
        const int idxA = huv[baseA],     idxB = huv[baseA + 1];
        const float rA = hr[baseA],      rB   = hr[baseA + 1];

        float* rowA_s = stg   + hA*ROWSTR;
        float* rowB_s = stg   + hB*ROWSTR;
        float* rowA_o = ohist + hA*ROWSTR;
        float* rowB_o = ohist + hB*ROWSTR;

        ull aA[8], aB[8];

        // Layer 1: relu(W1 @ [e_uv, r] + b1)
        initacc(aA, bias + ob);
        initacc(aB, bias + ob);
        const float4* vA = reinterpret_cast<const float4*>(v2e + (size_t)idxA * 64);
        const float4* vB = reinterpret_cast<const float4*>(v2e + (size_t)idxB * 64);
#pragma unroll 4
        for (int q4 = 0; q4 < 16; q4++) {
            float4 xa = vA[q4], xb = vB[q4];
            fstep(aA, aB, w1T + (4*q4 + 0)*64 + ob, xa.x, xb.x);
            fstep(aA, aB, w1T + (4*q4 + 1)*64 + ob, xa.y, xb.y);
            fstep(aA, aB, w1T + (4*q4 + 2)*64 + ob, xa.z, xb.z);
            fstep(aA, aB, w1T + (4*q4 + 3)*64 + ob, xa.w, xb.w);
        }
        fstep(aA, aB, w1T + 64*64 + ob, rA, rB);
        relustore(rowA_s + ob, aA);
        relustore(rowB_s + ob, aB);
        __syncwarp(gm);

        // Layer 2: o_hist = relu(W2 @ t + b2)  -> persists in ohist
        initacc(aA, bias + 64 + ob);
        initacc(aB, bias + 64 + ob);
        layer64(aA, aB, w2T, rowA_s, rowB_s, ob);
        relustore(rowA_o + ob, aA);
        relustore(rowB_o + ob, aB);
        __syncwarp(gm);

        // Layer 3: a1 = relu(A1[:, :64] @ o_hist + upart)   (urep half hoisted)
        initacc(aA, bias + 128 + ob);
        initacc(aB, bias + 128 + ob);
        layer64(aA, aB, a1T, rowA_o, rowB_o, ob);
        relustore(rowA_s + ob, aA);
        relustore(rowB_s + ob, aB);
        __syncwarp(gm);

        // Layer 4 + logit
        initacc(aA, bias + 192 + ob);
        initacc(aB, bias + 192 + ob);
        layer64(aA, aB, a2T, rowA_s, rowB_s, ob);
        float pA = 0.f, pB = 0.f;
#pragma unroll
        for (int j = 0; j < 8; j++) {
            float2 fa = upk(aA[j]), fb = upk(aB[j]);
            float w0 = bias[256 + ob + 2*j], w1v = bias[256 + ob + 2*j + 1];
            pA = fmaf(w0, fmaxf(fa.x, 0.f), pA); pA = fmaf(w1v, fmaxf(fa.y, 0.f), pA);
            pB = fmaf(w0, fmaxf(fb.x, 0.f), pB); pB = fmaf(w1v, fmaxf(fb.y, 0.f), pB);
        }
        pA += __shfl_xor_sync(gm, pA, 1);  pB += __shfl_xor_sync(gm, pB, 1);
        pA += __shfl_xor_sync(gm, pA, 2);  pB += __shfl_xor_sync(gm, pB, 2);
        if (q == 0) { lg[hA] = pA + bias[384]; lg[hB] = pB + bias[384]; }
    }
    __syncthreads();

    // ---- Softmax over h (block-wide, 16 warps) ----
    const int wid  = tid >> 5;
    const int lane = tid & 31;
    float v = (tid < 256) ? lg[tid] : -INFINITY;
#pragma unroll
    for (int s = 16; s; s >>= 1) v = fmaxf(v, __shfl_xor_sync(0xFFFFFFFFu, v, s));
    if (lane == 0) red[wid] = v;
    __syncthreads();
    if (tid == 0) {
        float m = red[0];
#pragma unroll
        for (int w = 1; w < 16; w++) m = fmaxf(m, red[w]);
        red[16] = m;
    }
    __syncthreads();
    const float maxv = red[16];
    float e = (tid < NH) ? expf(lg[tid] - maxv) : 0.0f;
    if (tid < 256) lg[tid] = e;
    float s = e;
#pragma unroll
    for (int sh = 16; sh; sh >>= 1) s += __shfl_xor_sync(0xFFFFFFFFu, s, sh);
    if (lane == 0) red[17 + wid] = s;
    __syncthreads();
    if (tid == 0) {
        float t = 0.0f;
#pragma unroll
        for (int w = 0; w < 16; w++) t += red[17 + w];
        red[33] = t;
    }
    __syncthreads();
    const float sumv = red[33];

    // ---- out[b, o] = sum_h e_h * o_hist[h][o] / sumv ----
    {
        const int o  = tid & 63;
        const int gr = tid >> 6;        // 8 groups over h
        float p = 0.0f;
        for (int hh = gr; hh < NH; hh += 8)
            p = fmaf(lg[hh], ohist[hh*ROWSTR + o], p);
        stg[gr*64 + o] = p;             // stg region is free now
    }
    __syncthreads();
    if (tid < 64) {
        float r8 = 0.0f;
#pragma unroll
        for (int gr = 0; gr < 8; gr++) r8 += stg[gr*64 + tid];
        out[(size_t)b * 64 + tid] = r8 / sumv;
    }
}

extern "C" void kernel_launch(void* const* d_in, const int* in_sizes, int n_in,
                              void* d_out, int out_size)
{
    const int*   nodes = (const int*)  d_in[0];
    const int*   huv   = (const int*)  d_in[1];
    const float* hr    = (const float*)d_in[2];
    const float* u2e   = (const float*)d_in[3];
    const float* v2e   = (const float*)d_in[4];
    const float* w1    = (const float*)d_in[5];
    const float* b1    = (const float*)d_in[6];
    const float* w2    = (const float*)d_in[7];
    const float* b2    = (const float*)d_in[8];
    const float* a1w   = (const float*)d_in[9];
    const float* a1b   = (const float*)d_in[10];
    const float* a2w   = (const float*)d_in[11];
    const float* a2b   = (const float*)d_in[12];
    const float* a3w   = (const float*)d_in[13];
    const float* a3b   = (const float*)d_in[14];
    float* out = (float*)d_out;

    cudaFuncSetAttribute(uvagg_kernel,
                         cudaFuncAttributeMaxDynamicSharedMemorySize, SMEM_BYTES);
    uvagg_kernel<<<NB, 512, SMEM_BYTES>>>(nodes, huv, hr, u2e, v2e,
                                          w1, b1, w2, b2,
                                          a1w, a1b, a2w, a2b, a3w, a3b, out);
}

// round 5
// speedup vs baseline: 1.6717x; 1.6717x over previous
#include <cuda_runtime.h>
#include <math.h>

#define NB   4096
#define NH   200
#define NROW 208      // padded rows (26 octets of 8)
#define NOCT 26
#define RS   212      // activation row stride (floats), 16B aligned
#define NTHR 320
#define NW   10

typedef unsigned long long ull;

__device__ __forceinline__ ull pk2(float a) {
    ull r; asm("mov.b64 %0, {%1, %1};" : "=l"(r) : "f"(a)); return r;
}
__device__ __forceinline__ float2 upk(ull v) {
    float2 f; asm("mov.b64 {%0, %1}, %2;" : "=f"(f.x), "=f"(f.y) : "l"(v)); return f;
}
__device__ __forceinline__ void ffma2(ull& d, ull a, ull b) {
    asm("fma.rn.f32x2 %0, %1, %2, %0;" : "+l"(d) : "l"(a), "l"(b));
}
__device__ __forceinline__ float4 relu4(ull p0, ull p1) {
    float2 f0 = upk(p0), f1 = upk(p1);
    return make_float4(fmaxf(f0.x, 0.f), fmaxf(f0.y, 0.f),
                       fmaxf(f1.x, 0.f), fmaxf(f1.y, 0.f));
}

// Fill k-major weight buffer WS[k*64+o] from o-major gmem w[o*wstride+k].
// Coalesced gmem reads when wstride==NIN (w1,w2,a2w); a1w reads first 64 cols.
template<int NIN>
__device__ __forceinline__ void fillWS(float* WS, const float* __restrict__ wg,
                                       int wstride, int tid) {
    for (int t = tid; t < 64 * NIN; t += NTHR) {
        int o = t / NIN, k = t - o * NIN;
        WS[k * 64 + o] = __ldg(wg + o * wstride + k);
    }
}

// One layer: lane owns output columns o1=lane, o2=lane+32.
// Preload weights from WS via conflict-free LDS.32 (lane==bank), then per
// octet of 8 rows: per input 2 broadcast LDS.128 + 8 FFMA2 (8 indep chains).
template<int NIN>
__device__ __forceinline__ void stage(const float* __restrict__ WS,
                                      const float* __restrict__ bs,
                                      const float* __restrict__ xs,
                                      float* __restrict__ ys,
                                      int lane, int wp)
{
    const int o1 = lane, o2 = lane + 32;
    float wA[NIN], wB[NIN];
#pragma unroll
    for (int k = 0; k < NIN; k++) {
        wA[k] = WS[k * 64 + o1];
        wB[k] = WS[k * 64 + o2];
    }
    const ull bA = pk2(bs[o1]);
    const ull bB = pk2(bs[o2]);

    for (int oc = wp; oc < NOCT; oc += NW) {
        const int rb = oc * 8;
        ull a0 = bA, a1 = bA, a2 = bA, a3 = bA;
        ull c0 = bB, c1 = bB, c2 = bB, c3 = bB;
#pragma unroll
        for (int i = 0; i < NIN; i++) {
            ulonglong2 x01 = *reinterpret_cast<const ulonglong2*>(xs + i * RS + rb);
            ulonglong2 x23 = *reinterpret_cast<const ulonglong2*>(xs + i * RS + rb + 4);
            ull wa = pk2(wA[i]);
            ull wb = pk2(wB[i]);
            ffma2(a0, x01.x, wa); ffma2(a1, x01.y, wa);
            ffma2(a2, x23.x, wa); ffma2(a3, x23.y, wa);
            ffma2(c0, x01.x, wb); ffma2(c1, x01.y, wb);
            ffma2(c2, x23.x, wb); ffma2(c3, x23.y, wb);
        }
        float4* d1 = reinterpret_cast<float4*>(ys + o1 * RS + rb);
        float4* d2 = reinterpret_cast<float4*>(ys + o2 * RS + rb);
        d1[0] = relu4(a0, a1);  d1[1] = relu4(a2, a3);
        d2[0] = relu4(c0, c1);  d2[1] = relu4(c2, c3);
    }
}

// SMEM (floats): WS 4160 | X 65*RS | Y 64*RS | O 64*RS | BS 400 | LG 256 | RED 64
#define SM_WS   0
#define SM_X    4160
#define SM_Y    (SM_X + 65 * RS)
#define SM_O    (SM_Y + 64 * RS)
#define SM_BS   (SM_O + 64 * RS)
#define SM_LG   (SM_BS + 400)
#define SM_RED  (SM_LG + 256)
#define SMEM_FLOATS (SM_RED + 64)
#define SMEM_BYTES  (SMEM_FLOATS * 4)

__global__ __launch_bounds__(NTHR, 1)
void uvagg_kernel(const int* __restrict__ nodes, const int* __restrict__ huv,
                  const float* __restrict__ hr,
                  const float* __restrict__ u2e, const float* __restrict__ v2e,
                  const float* __restrict__ w1, const float* __restrict__ b1,
                  const float* __restrict__ w2, const float* __restrict__ b2,
                  const float* __restrict__ a1w, const float* __restrict__ a1b,
                  const float* __restrict__ a2w, const float* __restrict__ a2b,
                  const float* __restrict__ a3w, const float* __restrict__ a3b,
                  float* __restrict__ out)
{
    extern __shared__ float sm[];
    float* WS  = sm + SM_WS;
    float* X   = sm + SM_X;
    float* Y   = sm + SM_Y;
    float* O   = sm + SM_O;
    float* BS  = sm + SM_BS;
    float* LG  = sm + SM_LG;
    float* RED = sm + SM_RED;

    const int tid  = threadIdx.x;
    const int lane = tid & 31;
    const int wp   = tid >> 5;
    const int b    = blockIdx.x;

    // ---- bias / urep staging ----
    if (tid < 64) {
        BS[tid]       = b1[tid];
        BS[64 + tid]  = b2[tid];
        BS[192 + tid] = a2b[tid];
        BS[256 + tid] = a3w[tid];
        BS[320 + tid] = u2e[(size_t)nodes[b] * 64 + tid];
    }
    if (tid == 0) BS[384] = a3b[0];
    if (tid >= 200 && tid < 256) LG[tid] = -INFINITY;
    __syncthreads();

    // ---- fill WS with w1; upart; gather X (all concurrent, disjoint SMEM) ----
    fillWS<65>(WS, w1, 65, tid);

    if (tid < 64) {  // upart[o] = a1b[o] + sum_i urep[i]*A1[o][64+i]
        const float4* ar = reinterpret_cast<const float4*>(a1w + tid * 128 + 64);
        float s = a1b[tid];
#pragma unroll
        for (int q = 0; q < 16; q++) {
            float4 w4 = ar[q];
            s = fmaf(BS[320 + 4*q + 0], w4.x, s);
            s = fmaf(BS[320 + 4*q + 1], w4.y, s);
            s = fmaf(BS[320 + 4*q + 2], w4.z, s);
            s = fmaf(BS[320 + 4*q + 3], w4.w, s);
        }
        BS[128 + tid] = s;
    }

    if (tid < NROW) {  // X_T[i][h] = v2e[huv[b,h]][i]; X_T[64][h]=r; pads zero
        const int h = tid;
        if (h < NH) {
            const long base = (long)b * NH + h;
            const int idx = huv[base];
            const float rv = hr[base];
            const float4* vr = reinterpret_cast<const float4*>(v2e + (size_t)idx * 64);
#pragma unroll
            for (int q = 0; q < 16; q++) {
                float4 v = vr[q];
                X[(4*q + 0) * RS + h] = v.x;
                X[(4*q + 1) * RS + h] = v.y;
                X[(4*q + 2) * RS + h] = v.z;
                X[(4*q + 3) * RS + h] = v.w;
            }
            X[64 * RS + h] = rv;
        } else {
#pragma unroll
            for (int i = 0; i < 65; i++) X[i * RS + h] = 0.0f;
        }
    }
    __syncthreads();

    // ---- layer chain: fill -> sync -> stage -> sync -> fill ... ----
    stage<65>(WS, BS + 0, X, Y, lane, wp);          // L1: X -> Y
    __syncthreads();
    fillWS<64>(WS, w2, 64, tid);
    __syncthreads();
    stage<64>(WS, BS + 64, Y, O, lane, wp);         // L2: Y -> O (persists)
    __syncthreads();
    fillWS<64>(WS, a1w, 128, tid);                  // first 64 cols of A1
    __syncthreads();
    stage<64>(WS, BS + 128, O, Y, lane, wp);        // L3: O -> Y (urep hoisted)
    __syncthreads();
    fillWS<64>(WS, a2w, 64, tid);
    __syncthreads();
    stage<64>(WS, BS + 192, Y, X, lane, wp);        // L4: Y -> X (reuse)
    __syncthreads();

    // ---- logits: lg[h] = a3b + sum_o a3w[o] * a2relu_T[o][h] ----
    if (tid < NH) {
        float s = BS[384];
#pragma unroll 8
        for (int o = 0; o < 64; o++) s = fmaf(BS[256 + o], X[o * RS + tid], s);
        LG[tid] = s;
    }
    __syncthreads();

    // ---- softmax over h ----
    float v = (tid < 256) ? LG[tid] : -INFINITY;
#pragma unroll
    for (int s = 16; s; s >>= 1) v = fmaxf(v, __shfl_xor_sync(0xFFFFFFFFu, v, s));
    if (lane == 0 && wp < 8) RED[wp] = v;
    __syncthreads();
    if (tid == 0) {
        float m = RED[0];
#pragma unroll
        for (int w = 1; w < 8; w++) m = fmaxf(m, RED[w]);
        RED[16] = m;
    }
    __syncthreads();
    const float maxv = RED[16];
    float e = (tid < NH) ? expf(LG[tid] - maxv) : 0.0f;
    if (tid < 256) LG[tid] = e;
    float ssum = e;
#pragma unroll
    for (int sh = 16; sh; sh >>= 1) ssum += __shfl_xor_sync(0xFFFFFFFFu, ssum, sh);
    if (lane == 0 && wp < 8) RED[17 + wp] = ssum;
    __syncthreads();
    if (tid == 0) {
        float t = 0.0f;
#pragma unroll
        for (int w = 0; w < 8; w++) t += RED[17 + w];
        RED[33] = t;
    }
    __syncthreads();

    // ---- out[b,o] = sum_h e_h * O_T[o][h] / sum ----
    {
        const int o = tid & 63;
        const int g = tid >> 6;          // 5 groups over h
        float p = 0.0f;
        for (int h = g; h < NH; h += 5)
            p = fmaf(LG[h], O[o * RS + h], p);
        Y[g * 64 + o] = p;               // Y free now
    }
    __syncthreads();
    if (tid < 64) {
        float r = Y[tid] + Y[64 + tid] + Y[128 + tid] + Y[192 + tid] + Y[256 + tid];
        out[(size_t)b * 64 + tid] = r / RED[33];
    }
}

extern "C" void kernel_launch(void* const* d_in, const int* in_sizes, int n_in,
                              void* d_out, int out_size)
{
    const int*   nodes = (const int*)  d_in[0];
    const int*   huv   = (const int*)  d_in[1];
    const float* hr    = (const float*)d_in[2];
    const float* u2e   = (const float*)d_in[3];
    const float* v2e   = (const float*)d_in[4];
    const float* w1    = (const float*)d_in[5];
    const float* b1    = (const float*)d_in[6];
    const float* w2    = (const float*)d_in[7];
    const float* b2    = (const float*)d_in[8];
    const float* a1w   = (const float*)d_in[9];
    const float* a1b   = (const float*)d_in[10];
    const float* a2w   = (const float*)d_in[11];
    const float* a2b   = (const float*)d_in[12];
    const float* a3w   = (const float*)d_in[13];
    const float* a3b   = (const float*)d_in[14];
    float* out = (float*)d_out;

    cudaFuncSetAttribute(uvagg_kernel,
                         cudaFuncAttributeMaxDynamicSharedMemorySize, SMEM_BYTES);
    uvagg_kernel<<<NB, NTHR, SMEM_BYTES>>>(nodes, huv, hr, u2e, v2e,
                                           w1, b1, w2, b2,
                                           a1w, a1b, a2w, a2b, a3w, a3b, out);
}

// round 6
// speedup vs baseline: 1.8207x; 1.0891x over previous
#include <cuda_runtime.h>
#include <math.h>

#define NB   4096
#define NH   200
#define NROW 208      // padded rows (26 octets of 8)
#define NOCT 26
#define RS   212      // activation row stride (floats), 16B aligned
#define NTHR 640
#define WSSTR 65      // weight smem stride (odd -> conflict-free preload)

typedef unsigned long long ull;

__device__ __forceinline__ ull pk2(float a) {
    ull r; asm("mov.b64 %0, {%1, %1};" : "=l"(r) : "f"(a)); return r;
}
__device__ __forceinline__ float2 upk(ull v) {
    float2 f; asm("mov.b64 {%0, %1}, %2;" : "=f"(f.x), "=f"(f.y) : "l"(v)); return f;
}
__device__ __forceinline__ void ffma2(ull& d, ull a, ull b) {
    asm("fma.rn.f32x2 %0, %1, %2, %0;" : "+l"(d) : "l"(a), "l"(b));
}
__device__ __forceinline__ float4 relu4(ull p0, ull p1) {
    float2 f0 = upk(p0), f1 = upk(p1);
    return make_float4(fmaxf(f0.x, 0.f), fmaxf(f0.y, 0.f),
                       fmaxf(f1.x, 0.f), fmaxf(f1.y, 0.f));
}
__device__ __forceinline__ unsigned sm_u32(const void* p) {
    unsigned a;
    asm("{ .reg .u64 t; cvta.to.shared.u64 t, %1; cvt.u32.u64 %0, t; }"
        : "=r"(a) : "l"(p));
    return a;
}
__device__ __forceinline__ void cpa4(unsigned dst, const float* src) {
    asm volatile("cp.async.ca.shared.global [%0], [%1], 4;" :: "r"(dst), "l"(src));
}
#define CPA_COMMIT() asm volatile("cp.async.commit_group;" ::: "memory")
#define CPA_WAIT0()  asm volatile("cp.async.wait_group 0;" ::: "memory")

// Async-fill WS[o*65+k] (o<64, k<NIN) from o-major gmem w[o*wstride+k].
template<int NIN>
__device__ __forceinline__ void fillWS_async(float* WS, const float* __restrict__ wg,
                                             int wstride, int tid) {
    unsigned base = sm_u32(WS);
    for (int t = tid; t < 64 * NIN; t += NTHR) {
        int o = t / NIN, k = t - o * NIN;
        cpa4(base + (unsigned)(o * WSSTR + k) * 4u, wg + o * wstride + k);
    }
}

// One layer. Lane owns single output column o. Weights preloaded to regs from
// WS (stride-65, conflict-free). Per octet of 8 rows: per input 2 broadcast
// LDS.128 + 4 FFMA2 over 4 independent f32x2 chains.
template<int NIN>
__device__ __forceinline__ void stage(const float* __restrict__ WS,
                                      const float* __restrict__ bs,
                                      const float* __restrict__ xs,
                                      float* __restrict__ ys,
                                      int o, int wo)
{
    float w[NIN];
#pragma unroll
    for (int k = 0; k < NIN; k++) w[k] = WS[o * WSSTR + k];
    const ull bb = pk2(bs[o]);

    for (int oc = wo; oc < NOCT; oc += 10) {
        const int rb = oc * 8;
        ull a0 = bb, a1 = bb, a2 = bb, a3 = bb;
#pragma unroll
        for (int i = 0; i < NIN; i++) {
            ulonglong2 x01 = *reinterpret_cast<const ulonglong2*>(xs + i * RS + rb);
            ulonglong2 x23 = *reinterpret_cast<const ulonglong2*>(xs + i * RS + rb + 4);
            ull wa = pk2(w[i]);
            ffma2(a0, x01.x, wa); ffma2(a1, x01.y, wa);
            ffma2(a2, x23.x, wa); ffma2(a3, x23.y, wa);
        }
        float4* d = reinterpret_cast<float4*>(ys + o * RS + rb);
        d[0] = relu4(a0, a1);
        d[1] = relu4(a2, a3);
    }
}

// SMEM (floats): WS0 4160 | WS1 4160 | X 65*RS | Y 64*RS | O 64*RS | BS 400 | LG 256 | RED 64
#define SM_WS0  0
#define SM_WS1  4160
#define SM_X    8320
#define SM_Y    (SM_X + 65 * RS)
#define SM_O    (SM_Y + 64 * RS)
#define SM_BS   (SM_O + 64 * RS)
#define SM_LG   (SM_BS + 400)
#define SM_RED  (SM_LG + 256)
#define SMEM_FLOATS (SM_RED + 64)
#define SMEM_BYTES  (SMEM_FLOATS * 4)

__global__ __launch_bounds__(NTHR, 1)
void uvagg_kernel(const int* __restrict__ nodes, const int* __restrict__ huv,
                  const float* __restrict__ hr,
                  const float* __restrict__ u2e, const float* __restrict__ v2e,
                  const float* __restrict__ w1, const float* __restrict__ b1,
                  const float* __restrict__ w2, const float* __restrict__ b2,
                  const float* __restrict__ a1w, const float* __restrict__ a1b,
                  const float* __restrict__ a2w, const float* __restrict__ a2b,
                  const float* __restrict__ a3w, const float* __restrict__ a3b,
                  float* __restrict__ out)
{
    extern __shared__ float sm[];
    float* WS0 = sm + SM_WS0;
    float* WS1 = sm + SM_WS1;
    float* X   = sm + SM_X;
    float* Y   = sm + SM_Y;
    float* O   = sm + SM_O;
    float* BS  = sm + SM_BS;
    float* LG  = sm + SM_LG;
    float* RED = sm + SM_RED;

    const int tid  = threadIdx.x;
    const int lane = tid & 31;
    const int wp   = tid >> 5;
    const int half = (wp >= 10);
    const int wo   = half ? (wp - 10) : wp;   // 0..9 within half
    const int ocol = half * 32 + lane;        // owned output column
    const int b    = blockIdx.x;

    // ---- kick off async fill of WS0 <- w1 (identity layout: stride 65 both) ----
    fillWS_async<65>(WS0, w1, 65, tid);
    CPA_COMMIT();

    // ---- bias / urep staging ----
    if (tid < 64) {
        BS[tid]       = b1[tid];
        BS[64 + tid]  = b2[tid];
        BS[192 + tid] = a2b[tid];
        BS[256 + tid] = a3w[tid];
        BS[320 + tid] = u2e[(size_t)nodes[b] * 64 + tid];
    }
    if (tid == 0) BS[384] = a3b[0];
    if (tid >= 200 && tid < 256) LG[tid] = -INFINITY;
    __syncthreads();

    // ---- upart[o] = a1b[o] + sum_i urep[i]*A1[o][64+i] ----
    if (tid < 64) {
        const float4* ar = reinterpret_cast<const float4*>(a1w + tid * 128 + 64);
        float s = a1b[tid];
#pragma unroll
        for (int q = 0; q < 16; q++) {
            float4 w4 = ar[q];
            s = fmaf(BS[320 + 4*q + 0], w4.x, s);
            s = fmaf(BS[320 + 4*q + 1], w4.y, s);
            s = fmaf(BS[320 + 4*q + 2], w4.z, s);
            s = fmaf(BS[320 + 4*q + 3], w4.w, s);
        }
        BS[128 + tid] = s;
    }

    // ---- gather X_T: 2 threads per row ----
    if (tid < 2 * NROW) {
        const int h = tid >> 1, part = tid & 1;
        if (h < NH) {
            const long base = (long)b * NH + h;
            const int idx = huv[base];
            const float4* vr = reinterpret_cast<const float4*>(v2e + (size_t)idx * 64);
#pragma unroll
            for (int q = 0; q < 8; q++) {
                float4 v = vr[part * 8 + q];
                const int i0 = (part * 8 + q) * 4;
                X[(i0 + 0) * RS + h] = v.x;
                X[(i0 + 1) * RS + h] = v.y;
                X[(i0 + 2) * RS + h] = v.z;
                X[(i0 + 3) * RS + h] = v.w;
            }
            if (part) X[64 * RS + h] = hr[base];
        } else {
            const int i0 = part ? 33 : 0, i1 = part ? 65 : 33;
            for (int i = i0; i < i1; i++) X[i * RS + h] = 0.0f;
        }
    }
    CPA_WAIT0();
    __syncthreads();

    // ---- L1 (WS0), prefetch w2 -> WS1 ----
    fillWS_async<64>(WS1, w2, 64, tid);
    CPA_COMMIT();
    stage<65>(WS0, BS + 0, X, Y, ocol, wo);
    CPA_WAIT0();
    __syncthreads();

    // ---- L2 (WS1), prefetch a1w[:, :64] -> WS0 ----
    fillWS_async<64>(WS0, a1w, 128, tid);
    CPA_COMMIT();
    stage<64>(WS1, BS + 64, Y, O, ocol, wo);     // -> o_history (persists)
    CPA_WAIT0();
    __syncthreads();

    // ---- L3 (WS0), prefetch a2w -> WS1 ----
    fillWS_async<64>(WS1, a2w, 64, tid);
    CPA_COMMIT();
    stage<64>(WS0, BS + 128, O, Y, ocol, wo);    // urep half hoisted into bias
    CPA_WAIT0();
    __syncthreads();

    // ---- L4 (WS1) ----
    stage<64>(WS1, BS + 192, Y, X, ocol, wo);
    __syncthreads();

    // ---- logits ----
    if (tid < NH) {
        float s = BS[384];
#pragma unroll 8
        for (int o = 0; o < 64; o++) s = fmaf(BS[256 + o], X[o * RS + tid], s);
        LG[tid] = s;
    }
    __syncthreads();

    // ---- softmax over h ----
    float v = (tid < 256) ? LG[tid] : -INFINITY;
#pragma unroll
    for (int s = 16; s; s >>= 1) v = fmaxf(v, __shfl_xor_sync(0xFFFFFFFFu, v, s));
    if (lane == 0 && wp < 8) RED[wp] = v;
    __syncthreads();
    if (tid == 0) {
        float m = RED[0];
#pragma unroll
        for (int w = 1; w < 8; w++) m = fmaxf(m, RED[w]);
        RED[16] = m;
    }
    __syncthreads();
    const float maxv = RED[16];
    float e = (tid < NH) ? expf(LG[tid] - maxv) : 0.0f;
    if (tid < 256) LG[tid] = e;
    float ssum = e;
#pragma unroll
    for (int sh = 16; sh; sh >>= 1) ssum += __shfl_xor_sync(0xFFFFFFFFu, ssum, sh);
    if (lane == 0 && wp < 8) RED[17 + wp] = ssum;
    __syncthreads();
    if (tid == 0) {
        float t = 0.0f;
#pragma unroll
        for (int w = 0; w < 8; w++) t += RED[17 + w];
        RED[33] = t;
    }
    __syncthreads();

    // ---- out[b,o] = sum_h e_h * O_T[o][h] / sum (10 h-groups) ----
    {
        const int o = tid & 63;
        const int g = tid >> 6;          // 0..9
        float p = 0.0f;
        for (int h = g; h < NH; h += 10)
            p = fmaf(LG[h], O[o * RS + h], p);
        Y[g * 64 + o] = p;               // Y free now
    }
    __syncthreads();
    if (tid < 64) {
        float r = 0.0f;
#pragma unroll
        for (int g = 0; g < 10; g++) r += Y[g * 64 + tid];
        out[(size_t)b * 64 + tid] = r / RED[33];
    }
}

extern "C" void kernel_launch(void* const* d_in, const int* in_sizes, int n_in,
                              void* d_out, int out_size)
{
    const int*   nodes = (const int*)  d_in[0];
    const int*   huv   = (const int*)  d_in[1];
    const float* hr    = (const float*)d_in[2];
    const float* u2e   = (const float*)d_in[3];
    const float* v2e   = (const float*)d_in[4];
    const float* w1    = (const float*)d_in[5];
    const float* b1    = (const float*)d_in[6];
    const float* w2    = (const float*)d_in[7];
    const float* b2    = (const float*)d_in[8];
    const float* a1w   = (const float*)d_in[9];
    const float* a1b   = (const float*)d_in[10];
    const float* a2w   = (const float*)d_in[11];
    const float* a2b   = (const float*)d_in[12];
    const float* a3w   = (const float*)d_in[13];
    const float* a3b   = (const float*)d_in[14];
    float* out = (float*)d_out;

    cudaFuncSetAttribute(uvagg_kernel,
                         cudaFuncAttributeMaxDynamicSharedMemorySize, SMEM_BYTES);
    uvagg_kernel<<<NB, NTHR, SMEM_BYTES>>>(nodes, huv, hr, u2e, v2e,
                                           w1, b1, w2, b2,
                                           a1w, a1b, a2w, a2b, a3w, a3b, out);
}

// round 7
// speedup vs baseline: 2.3985x; 1.3174x over previous
#include <cuda_runtime.h>
#include <math.h>

#define NB   4096
#define NH   200
#define NROW 208      // padded rows (52 quartets of 4)
#define NQRT 52
#define RS   212      // activation row stride (floats), 16B aligned
#define NTHR 384
#define NWARP 12
#define WSSTR 65      // weight smem stride (odd -> conflict-free preload)

typedef unsigned long long ull;

__device__ __forceinline__ ull pk2(float a) {
    ull r; asm("mov.b64 %0, {%1, %1};" : "=l"(r) : "f"(a)); return r;
}
__device__ __forceinline__ float2 upk(ull v) {
    float2 f; asm("mov.b64 {%0, %1}, %2;" : "=f"(f.x), "=f"(f.y) : "l"(v)); return f;
}
__device__ __forceinline__ void ffma2(ull& d, ull a, ull b) {
    asm("fma.rn.f32x2 %0, %1, %2, %0;" : "+l"(d) : "l"(a), "l"(b));
}
__device__ __forceinline__ float4 relu4(ull p0, ull p1) {
    float2 f0 = upk(p0), f1 = upk(p1);
    return make_float4(fmaxf(f0.x, 0.f), fmaxf(f0.y, 0.f),
                       fmaxf(f1.x, 0.f), fmaxf(f1.y, 0.f));
}
__device__ __forceinline__ unsigned sm_u32(const void* p) {
    unsigned a;
    asm("{ .reg .u64 t; cvta.to.shared.u64 t, %1; cvt.u32.u64 %0, t; }"
        : "=r"(a) : "l"(p));
    return a;
}
__device__ __forceinline__ void cpa4(unsigned dst, const float* src) {
    asm volatile("cp.async.ca.shared.global [%0], [%1], 4;" :: "r"(dst), "l"(src));
}
#define CPA_COMMIT() asm volatile("cp.async.commit_group;" ::: "memory")
#define CPA_WAIT0()  asm volatile("cp.async.wait_group 0;" ::: "memory")

// Async-fill WS[o*65+k] (o<64, k<NIN) from o-major gmem w[o*wstride+k].
template<int NIN>
__device__ __forceinline__ void fillWS_async(float* WS, const float* __restrict__ wg,
                                             int wstride, int tid) {
    unsigned base = sm_u32(WS);
    for (int t = tid; t < 64 * NIN; t += NTHR) {
        int o = t / NIN, k = t - o * NIN;
        cpa4(base + (unsigned)(o * WSSTR + k) * 4u, wg + o * wstride + k);
    }
}

// One layer. Lane owns output columns o1=lane, o2=lane+32 (weights in regs,
// preloaded conflict-free from stride-65 WS). Per quartet of 4 rows, per input:
// 1 broadcast LDS.128 + 4 FFMA2 (1:4 reuse, 4 independent chains).
template<int NIN>
__device__ __forceinline__ void stage(const float* __restrict__ WS,
                                      const float* __restrict__ bs,
                                      const float* __restrict__ xs,
                                      float* __restrict__ ys,
                                      int lane, int wp)
{
    const int o1 = lane, o2 = lane + 32;
    float wA[NIN], wB[NIN];
#pragma unroll
    for (int k = 0; k < NIN; k++) {
        wA[k] = WS[o1 * WSSTR + k];
        wB[k] = WS[o2 * WSSTR + k];
    }
    const ull bA = pk2(bs[o1]);
    const ull bB = pk2(bs[o2]);

    for (int q = wp; q < NQRT; q += NWARP) {
        const int rb = q * 4;
        ull a0 = bA, a1 = bA;
        ull c0 = bB, c1 = bB;
#pragma unroll
        for (int i = 0; i < NIN; i++) {
            ulonglong2 x = *reinterpret_cast<const ulonglong2*>(xs + i * RS + rb);
            ull wa = pk2(wA[i]);
            ull wb = pk2(wB[i]);
            ffma2(a0, x.x, wa); ffma2(a1, x.y, wa);
            ffma2(c0, x.x, wb); ffma2(c1, x.y, wb);
        }
        *reinterpret_cast<float4*>(ys + o1 * RS + rb) = relu4(a0, a1);
        *reinterpret_cast<float4*>(ys + o2 * RS + rb) = relu4(c0, c1);
    }
}

// SMEM (floats): WS0 4160 | WS1 4160 | X 65*RS | Y 64*RS | O 64*RS | BS 400 | LG 256 | RED 64
#define SM_WS0  0
#define SM_WS1  4160
#define SM_X    8320
#define SM_Y    (SM_X + 65 * RS)
#define SM_O    (SM_Y + 64 * RS)
#define SM_BS   (SM_O + 64 * RS)
#define SM_LG   (SM_BS + 400)
#define SM_RED  (SM_LG + 256)
#define SMEM_FLOATS (SM_RED + 64)
#define SMEM_BYTES  (SMEM_FLOATS * 4)

__global__ __launch_bounds__(NTHR, 1)
void uvagg_kernel(const int* __restrict__ nodes, const int* __restrict__ huv,
                  const float* __restrict__ hr,
                  const float* __restrict__ u2e, const float* __restrict__ v2e,
                  const float* __restrict__ w1, const float* __restrict__ b1,
                  const float* __restrict__ w2, const float* __restrict__ b2,
                  const float* __restrict__ a1w, const float* __restrict__ a1b,
                  const float* __restrict__ a2w, const float* __restrict__ a2b,
                  const float* __restrict__ a3w, const float* __restrict__ a3b,
                  float* __restrict__ out)
{
    extern __shared__ float sm[];
    float* WS0 = sm + SM_WS0;
    float* WS1 = sm + SM_WS1;
    float* X   = sm + SM_X;
    float* Y   = sm + SM_Y;
    float* O   = sm + SM_O;
    float* BS  = sm + SM_BS;
    float* LG  = sm + SM_LG;
    float* RED = sm + SM_RED;

    const int tid  = threadIdx.x;
    const int lane = tid & 31;
    const int wp   = tid >> 5;
    const int b    = blockIdx.x;

    // ---- kick off async fill of WS0 <- w1 (identity layout: stride 65 both) ----
    fillWS_async<65>(WS0, w1, 65, tid);
    CPA_COMMIT();

    // ---- bias / urep staging ----
    if (tid < 64) {
        BS[tid]       = b1[tid];
        BS[64 + tid]  = b2[tid];
        BS[192 + tid] = a2b[tid];
        BS[256 + tid] = a3w[tid];
        BS[320 + tid] = u2e[(size_t)nodes[b] * 64 + tid];
    }
    if (tid == 0) BS[384] = a3b[0];
    if (tid >= 200 && tid < 256) LG[tid] = -INFINITY;
    __syncthreads();

    // ---- upart[o] = a1b[o] + sum_i urep[i]*A1[o][64+i] ----
    if (tid < 64) {
        const float4* ar = reinterpret_cast<const float4*>(a1w + tid * 128 + 64);
        float s = a1b[tid];
#pragma unroll
        for (int q = 0; q < 16; q++) {
            float4 w4 = ar[q];
            s = fmaf(BS[320 + 4*q + 0], w4.x, s);
            s = fmaf(BS[320 + 4*q + 1], w4.y, s);
            s = fmaf(BS[320 + 4*q + 2], w4.z, s);
            s = fmaf(BS[320 + 4*q + 3], w4.w, s);
        }
        BS[128 + tid] = s;
    }

    // ---- gather X_T: 2 work-items per row, looped over 384 threads ----
    for (int t = tid; t < 2 * NROW; t += NTHR) {
        const int h = t >> 1, part = t & 1;
        if (h < NH) {
            const long base = (long)b * NH + h;
            const int idx = huv[base];
            const float4* vr = reinterpret_cast<const float4*>(v2e + (size_t)idx * 64);
#pragma unroll
            for (int q = 0; q < 8; q++) {
                float4 v = vr[part * 8 + q];
                const int i0 = (part * 8 + q) * 4;
                X[(i0 + 0) * RS + h] = v.x;
                X[(i0 + 1) * RS + h] = v.y;
                X[(i0 + 2) * RS + h] = v.z;
                X[(i0 + 3) * RS + h] = v.w;
            }
            if (part) X[64 * RS + h] = hr[base];
        } else {
            const int i0 = part ? 33 : 0, i1 = part ? 65 : 33;
            for (int i = i0; i < i1; i++) X[i * RS + h] = 0.0f;
        }
    }
    CPA_WAIT0();
    __syncthreads();

    // ---- L1 (WS0), prefetch w2 -> WS1 ----
    fillWS_async<64>(WS1, w2, 64, tid);
    CPA_COMMIT();
    stage<65>(WS0, BS + 0, X, Y, lane, wp);
    CPA_WAIT0();
    __syncthreads();

    // ---- L2 (WS1), prefetch a1w[:, :64] -> WS0 ----
    fillWS_async<64>(WS0, a1w, 128, tid);
    CPA_COMMIT();
    stage<64>(WS1, BS + 64, Y, O, lane, wp);     // -> o_history (persists)
    CPA_WAIT0();
    __syncthreads();

    // ---- L3 (WS0), prefetch a2w -> WS1 ----
    fillWS_async<64>(WS1, a2w, 64, tid);
    CPA_COMMIT();
    stage<64>(WS0, BS + 128, O, Y, lane, wp);    // urep half hoisted into bias
    CPA_WAIT0();
    __syncthreads();

    // ---- L4 (WS1) ----
    stage<64>(WS1, BS + 192, Y, X, lane, wp);
    __syncthreads();

    // ---- logits ----
    if (tid < NH) {
        float s = BS[384];
#pragma unroll 8
        for (int o = 0; o < 64; o++) s = fmaf(BS[256 + o], X[o * RS + tid], s);
        LG[tid] = s;
    }
    __syncthreads();

    // ---- softmax over h ----
    float v = (tid < 256) ? LG[tid] : -INFINITY;
#pragma unroll
    for (int s = 16; s; s >>= 1) v = fmaxf(v, __shfl_xor_sync(0xFFFFFFFFu, v, s));
    if (lane == 0 && wp < 8) RED[wp] = v;
    __syncthreads();
    if (tid == 0) {
        float m = RED[0];
#pragma unroll
        for (int w = 1; w < 8; w++) m = fmaxf(m, RED[w]);
        RED[16] = m;
    }
    __syncthreads();
    const float maxv = RED[16];
    float e = (tid < NH) ? expf(LG[tid] - maxv) : 0.0f;
    if (tid < 256) LG[tid] = e;
    float ssum = e;
#pragma unroll
    for (int sh = 16; sh; sh >>= 1) ssum += __shfl_xor_sync(0xFFFFFFFFu, ssum, sh);
    if (lane == 0 && wp < 8) RED[17 + wp] = ssum;
    __syncthreads();
    if (tid == 0) {
        float t = 0.0f;
#pragma unroll
        for (int w = 0; w < 8; w++) t += RED[17 + w];
        RED[33] = t;
    }
    __syncthreads();

    // ---- out[b,o] = sum_h e_h * O_T[o][h] / sum (6 h-groups) ----
    {
        const int o = tid & 63;
        const int g = tid >> 6;          // 0..5
        float p = 0.0f;
        for (int h = g; h < NH; h += 6)
            p = fmaf(LG[h], O[o * RS + h], p);
        Y[g * 64 + o] = p;               // Y free now
    }
    __syncthreads();
    if (tid < 64) {
        float r = 0.0f;
#pragma unroll
        for (int g = 0; g < 6; g++) r += Y[g * 64 + tid];
        out[(size_t)b * 64 + tid] = r / RED[33];
    }
}

extern "C" void kernel_launch(void* const* d_in, const int* in_sizes, int n_in,
                              void* d_out, int out_size)
{
    const int*   nodes = (const int*)  d_in[0];
    const int*   huv   = (const int*)  d_in[1];
    const float* hr    = (const float*)d_in[2];
    const float* u2e   = (const float*)d_in[3];
    const float* v2e   = (const float*)d_in[4];
    const float* w1    = (const float*)d_in[5];
    const float* b1    = (const float*)d_in[6];
    const float* w2    = (const float*)d_in[7];
    const float* b2    = (const float*)d_in[8];
    const float* a1w   = (const float*)d_in[9];
    const float* a1b   = (const float*)d_in[10];
    const float* a2w   = (const float*)d_in[11];
    const float* a2b   = (const float*)d_in[12];
    const float* a3w   = (const float*)d_in[13];
    const float* a3b   = (const float*)d_in[14];
    float* out = (float*)d_out;

    cudaFuncSetAttribute(uvagg_kernel,
                         cudaFuncAttributeMaxDynamicSharedMemorySize, SMEM_BYTES);
    uvagg_kernel<<<NB, NTHR, SMEM_BYTES>>>(nodes, huv, hr, u2e, v2e,
                                           w1, b1, w2, b2,
                                           a1w, a1b, a2w, a2b, a3w, a3b, out);
}